// round 2
// baseline (speedup 1.0000x reference)
#include <cuda_runtime.h>
#include <math_constants.h>

// Quantize (VQ-VAE) for GB300:
//   inputs:       (8,64,32,128) f32  -> 16384 samples x 128 dims
//   cluster_mean: (128,10000)   f32  -> codebook, d-major
//   out: 2097152 f32 outputs (straight-through) + 1 f32 loss
//
// dist = ||x||^2 - 2 x.c + ||c||^2 ; argmin over codes needs only (||c||^2 - 2 x.c).
// Full fp32 FFMA accumulation to match the fp32 reference argmin.

#define NS    16384          // samples
#define DD    128            // embed dim
#define NC    10000          // codes
#define TM    128            // sample tile
#define TN    128            // code tile
#define NT    ((NC + TN - 1) / TN)   // 79
#define NOUT  (NS * DD)      // 2097152
#define NBLK  (NOUT / 256)   // 8192 gather blocks

#define SMEM_BYTES ((2 * TM * DD + TN) * 4)   // Xs + Cs + Ns = 131584 B

__device__ float  g_norms[NC];
__device__ int    g_idx[NS];
__device__ double g_partial[NBLK];

// ---------------------------------------------------------------- code norms
__global__ void k_norms(const float* __restrict__ C) {
    int j = blockIdx.x * 256 + threadIdx.x;
    if (j >= NC) return;
    float s = 0.f;
#pragma unroll 8
    for (int d = 0; d < DD; d++) {
        float v = C[(size_t)d * NC + j];   // coalesced across j
        s = fmaf(v, v, s);
    }
    g_norms[j] = s;
}

// ------------------------------------------------- fused GEMM + argmin kernel
// Grid: 128 CTAs (one 128-sample tile each). 256 threads = 16x16.
// Each thread owns an 8x8 micro-tile (rows ty*4..+3 and 64+ty*4..+3,
// cols tx*4..+3 and 64+tx*4..+3). fp32 accumulators, running (min,idx).
__global__ __launch_bounds__(256, 1)
void k_argmin(const float* __restrict__ X, const float* __restrict__ C) {
    extern __shared__ float smem[];
    float* Xs = smem;                 // [d][i]  128x128
    float* Cs = smem + TM * DD;       // [d][j]  128x128
    float* Ns = smem + 2 * TM * DD;   // [j]     128

    const int tid = threadIdx.x;
    const int tx = tid & 15;
    const int ty = tid >> 4;
    const int sbase = blockIdx.x * TM;

    // Load X tile transposed: X[(sbase+i)*128 + d] -> Xs[d*TM + i]
    // (one-time 32-way STS conflicts, negligible vs 2.6M compute cycles)
    for (int r = tid; r < TM * DD / 4; r += 256) {
        int i  = r >> 5;
        int d4 = (r & 31) << 2;
        float4 v = *(const float4*)(X + (size_t)(sbase + i) * DD + d4);
        Xs[(d4 + 0) * TM + i] = v.x;
        Xs[(d4 + 1) * TM + i] = v.y;
        Xs[(d4 + 2) * TM + i] = v.z;
        Xs[(d4 + 3) * TM + i] = v.w;
    }

    float minv[8];
    int   mini[8];
#pragma unroll
    for (int r = 0; r < 8; r++) { minv[r] = CUDART_INF_F; mini[r] = 0; }

    for (int t = 0; t < NT; t++) {
        const int jbase = t * TN;
        __syncthreads();   // previous tile's Cs readers are done

        // Load C tile: C[d*NC + jbase + j] -> Cs[d*TN + j] (no transpose needed)
        if (jbase + TN <= NC) {
#pragma unroll 4
            for (int r = tid; r < TN * DD / 4; r += 256) {
                int d  = r >> 5;
                int j4 = (r & 31) << 2;
                *(float4*)(Cs + d * TN + j4) =
                    *(const float4*)(C + (size_t)d * NC + jbase + j4);
            }
        } else {           // ragged last tile (16 valid codes): guarded scalar
            for (int r = tid; r < TN * DD; r += 256) {
                int d = r >> 7;
                int j = r & 127;
                int jj = jbase + j;
                Cs[d * TN + j] = (jj < NC) ? C[(size_t)d * NC + jj] : 0.f;
            }
        }
        if (tid < TN) {
            int jj = jbase + tid;
            Ns[tid] = (jj < NC) ? g_norms[jj] : CUDART_INF_F;  // INF masks pad codes
        }
        __syncthreads();

        float acc[8][8];
#pragma unroll
        for (int r = 0; r < 8; r++)
#pragma unroll
            for (int c = 0; c < 8; c++) acc[r][c] = 0.f;

#pragma unroll 8
        for (int d = 0; d < DD; d++) {
            float4 a0 = *(const float4*)(Xs + d * TM + (ty << 2));
            float4 a1 = *(const float4*)(Xs + d * TM + 64 + (ty << 2));
            float4 b0 = *(const float4*)(Cs + d * TN + (tx << 2));
            float4 b1 = *(const float4*)(Cs + d * TN + 64 + (tx << 2));
            float a[8] = {a0.x, a0.y, a0.z, a0.w, a1.x, a1.y, a1.z, a1.w};
            float b[8] = {b0.x, b0.y, b0.z, b0.w, b1.x, b1.y, b1.z, b1.w};
#pragma unroll
            for (int r = 0; r < 8; r++)
#pragma unroll
                for (int c = 0; c < 8; c++)
                    acc[r][c] = fmaf(a[r], b[c], acc[r][c]);
        }

        // Epilogue: dist = n_j - 2*dot ; strict < + ascending j order keeps
        // the first index on ties (matches jnp.argmin).
#pragma unroll
        for (int c = 0; c < 8; c++) {
            int jl = (c < 4) ? ((tx << 2) + c) : (64 + (tx << 2) + (c - 4));
            float nv = Ns[jl];
            int jj = jbase + jl;
#pragma unroll
            for (int r = 0; r < 8; r++) {
                float val = fmaf(-2.f, acc[r][c], nv);
                if (val < minv[r]) { minv[r] = val; mini[r] = jj; }
            }
        }
    }

    // Cross-thread argmin reduction (16 tx candidates per sample row).
    __syncthreads();
    float* redv = Cs;                 // 128*16 floats
    int*   redi = (int*)(Cs + 2048);  // 128*16 ints
#pragma unroll
    for (int r = 0; r < 8; r++) {
        int i = (r < 4) ? ((ty << 2) + r) : (64 + (ty << 2) + (r - 4));
        redv[i * 16 + tx] = minv[r];
        redi[i * 16 + tx] = mini[r];
    }
    __syncthreads();
    if (tid < TM) {
        float bv = redv[tid * 16];
        int   bi = redi[tid * 16];
#pragma unroll
        for (int u = 1; u < 16; u++) {
            float v  = redv[tid * 16 + u];
            int   ix = redi[tid * 16 + u];
            if (v < bv || (v == bv && ix < bi)) { bv = v; bi = ix; }
        }
        g_idx[sbase + tid] = bi;
    }
}

// ------------------------------------- gather + straight-through + loss parts
__global__ void k_gather(const float* __restrict__ X, const float* __restrict__ C,
                         float* __restrict__ out) {
    int t = blockIdx.x * 256 + threadIdx.x;
    int i = t >> 7;     // sample
    int d = t & 127;    // dim (fast -> coalesced out writes)
    int j = g_idx[i];
    float x = X[t];
    float q = C[(size_t)d * NC + j];     // codebook resident in L2
    out[t] = x + (q - x);                // replicate reference rounding exactly
    float diff = q - x;
    float v = diff * diff;
#pragma unroll
    for (int off = 16; off > 0; off >>= 1)
        v += __shfl_down_sync(0xffffffffu, v, off);
    __shared__ float ws[8];
    int lane = threadIdx.x & 31, w = threadIdx.x >> 5;
    if (lane == 0) ws[w] = v;
    __syncthreads();
    if (threadIdx.x == 0) {
        double s = 0.0;
        for (int k = 0; k < 8; k++) s += (double)ws[k];
        g_partial[blockIdx.x] = s;       // deterministic (no atomics)
    }
}

// --------------------------------------------------- final deterministic loss
__global__ void k_loss(float* __restrict__ out, int loss_pos) {
    __shared__ double sm[256];
    double s = 0.0;
    for (int k = threadIdx.x; k < NBLK; k += 256) s += g_partial[k];
    sm[threadIdx.x] = s;
    __syncthreads();
    for (int off = 128; off > 0; off >>= 1) {
        if (threadIdx.x < off) sm[threadIdx.x] += sm[threadIdx.x + off];
        __syncthreads();
    }
    // loss = q_loss + 0.25*e_loss = 1.25 * mean((q - x)^2)
    if (threadIdx.x == 0 && loss_pos >= 0)
        out[loss_pos] = (float)(1.25 * sm[0] / (double)NOUT);
}

// ---------------------------------------------------------------------- entry
extern "C" void kernel_launch(void* const* d_in, const int* in_sizes, int n_in,
                              void* d_out, int out_size) {
    const float* X = (const float*)d_in[0];
    const float* C = (const float*)d_in[1];
    // Defensive: tolerate swapped metadata order (sizes are unambiguous).
    if (n_in >= 2 && in_sizes[0] == DD * NC && in_sizes[1] == NOUT) {
        const float* tmp = X; X = C; C = tmp;
    }
    float* out = (float*)d_out;

    cudaFuncSetAttribute(k_argmin, cudaFuncAttributeMaxDynamicSharedMemorySize,
                         SMEM_BYTES);

    k_norms<<<(NC + 255) / 256, 256>>>(C);
    k_argmin<<<NS / TM, 256, SMEM_BYTES>>>(X, C);
    k_gather<<<NBLK, 256>>>(X, C, out);

    int loss_pos = (out_size > NOUT) ? (out_size - 1) : -1;
    k_loss<<<1, 256>>>(out, loss_pos);
}